// round 5
// baseline (speedup 1.0000x reference)
#include <cuda_runtime.h>

// Problem constants
#define B_   4
#define N_   2048
#define FIN  256
#define H_   4
#define FO_  64
#define HF   256               // H_*FO_
#define M_   (B_*N_)           // 8192 rows of h
#define NH   (M_*H_)           // 32768 (node, head) pairs

// Scratch (device globals — no allocation allowed)
__device__ float g_h[M_ * HF];                      // h = x@W, 8 MB
__device__ float g_s[NH], g_dv[NH];
__device__ float g_A1[NH], g_A2[NH], g_E1[NH], g_E2[NH];

// ---------------- packed f32x2 helpers (Blackwell FFMA2) ----------------
__device__ __forceinline__ unsigned long long dup2(float x) {
    unsigned long long d;
    unsigned int u = __float_as_uint(x);
    asm("mov.b64 %0, {%1, %1};" : "=l"(d) : "r"(u));
    return d;
}
__device__ __forceinline__ void fma2(unsigned long long& acc,
                                     unsigned long long a, unsigned long long b) {
    asm("fma.rn.f32x2 %0, %1, %2, %0;" : "+l"(acc) : "l"(a), "l"(b));
}
__device__ __forceinline__ float2 unp2(unsigned long long v) {
    float2 r;
    asm("mov.b64 {%0, %1}, %2;" : "=f"(r.x), "=f"(r.y) : "l"(v));
    return r;
}

// ---------------- Kernel 1: h = x @ W  (8192x256 @ 256x256) ----------------
// 128x64 block tile, 128 threads, 8x8 microtile, BK=16.
__global__ __launch_bounds__(128) void gemm_kernel(const float* __restrict__ x,
                                                   const float* __restrict__ W) {
    __shared__ float As[16][132];   // As[k][m], padded
    __shared__ float Bs[16][68];    // Bs[k][n], padded

    const int t  = threadIdx.x;
    const int m0 = blockIdx.x * 128;
    const int n0 = blockIdx.y * 64;
    const int gm = t >> 3;          // 0..15 -> rows gm*8..+7
    const int gn = t & 7;           // 0..7  -> cols gn*8..+7

    float acc[8][8];
#pragma unroll
    for (int i = 0; i < 8; i++)
#pragma unroll
        for (int j = 0; j < 8; j++) acc[i][j] = 0.f;

    for (int k0 = 0; k0 < FIN; k0 += 16) {
        // stage loads into registers
        float4 xv[4];
        const float* xrow = x + (size_t)(m0 + t) * FIN + k0;
#pragma unroll
        for (int q = 0; q < 4; q++) xv[q] = *(const float4*)(xrow + 4 * q);

        float4 wv0, wv1;
        {
            const int kr = t >> 3;            // 0..15
            const int cp = (t & 7) * 8;       // 0..56
            const float* wrow = W + (size_t)(k0 + kr) * HF + n0 + cp;
            wv0 = *(const float4*)(wrow);
            wv1 = *(const float4*)(wrow + 4);
        }

        __syncthreads();   // previous compute finished reading smem
#pragma unroll
        for (int q = 0; q < 4; q++) {
            As[4 * q + 0][t] = xv[q].x;
            As[4 * q + 1][t] = xv[q].y;
            As[4 * q + 2][t] = xv[q].z;
            As[4 * q + 3][t] = xv[q].w;
        }
        {
            const int kr = t >> 3;
            const int cp = (t & 7) * 8;
            *(float4*)&Bs[kr][cp]     = wv0;
            *(float4*)&Bs[kr][cp + 4] = wv1;
        }
        __syncthreads();

#pragma unroll
        for (int kk = 0; kk < 16; kk++) {
            float a[8], b[8];
            *(float4*)(a)     = *(const float4*)&As[kk][gm * 8];
            *(float4*)(a + 4) = *(const float4*)&As[kk][gm * 8 + 4];
            *(float4*)(b)     = *(const float4*)&Bs[kk][gn * 8];
            *(float4*)(b + 4) = *(const float4*)&Bs[kk][gn * 8 + 4];
#pragma unroll
            for (int i = 0; i < 8; i++)
#pragma unroll
                for (int j = 0; j < 8; j++) acc[i][j] += a[i] * b[j];
        }
    }

#pragma unroll
    for (int i = 0; i < 8; i++) {
        float* orow = g_h + (size_t)(m0 + gm * 8 + i) * HF + n0 + gn * 8;
        *(float4*)(orow)     = make_float4(acc[i][0], acc[i][1], acc[i][2], acc[i][3]);
        *(float4*)(orow + 4) = make_float4(acc[i][4], acc[i][5], acc[i][6], acc[i][7]);
    }
}

// ---------------- Kernel 2: attention coefficients + exp factors ----------------
// warp per (node, head): s = h . a_src, d = h . a_dst, then exp factors.
__global__ __launch_bounds__(256) void attn_coef_kernel(const float* __restrict__ a_src,
                                                        const float* __restrict__ a_dst) {
    const int nh   = (blockIdx.x * blockDim.x + threadIdx.x) >> 5;   // (b*N+n)*H + head
    const int lane = threadIdx.x & 31;
    if (nh >= NH) return;
    const int head = nh & (H_ - 1);

    const float* hrow = g_h + (size_t)nh * FO_;
    const float v0 = hrow[lane];
    const float v1 = hrow[lane + 32];
    const float* as = a_src + head * FO_;
    const float* ad = a_dst + head * FO_;
    float ps = v0 * as[lane] + v1 * as[lane + 32];
    float pd = v0 * ad[lane] + v1 * ad[lane + 32];
#pragma unroll
    for (int o = 16; o > 0; o >>= 1) {
        ps += __shfl_xor_sync(0xffffffffu, ps, o);
        pd += __shfl_xor_sync(0xffffffffu, pd, o);
    }
    if (lane == 0) {
        g_s[nh]  = ps;
        g_A1[nh] = expf(ps);
        g_A2[nh] = expf(0.2f * ps);
        g_dv[nh] = pd;
        g_E1[nh] = expf(pd);
        g_E2[nh] = expf(0.2f * pd);
    }
}

// ---------------- Kernel 3: masked-softmax attention + P@V ----------------
// Block = (b, head, i-block of 128). 128 threads.
// Phase B: thread t owns row i=t -> weights + private denominator (no atomics).
// Phase C: thread -> 8i x 8f microtile, packed f32x2 FMAs.
#define TI 128
#define TJ 32

__global__ __launch_bounds__(128, 2) void gat_attn_kernel(const float* __restrict__ adj,
                                                          float* __restrict__ out) {
    __shared__ __align__(16) float h_s[TJ][68];     // 64 used + pad
    __shared__ __align__(16) float w_s[TJ][TI];
    __shared__ float d_s[TJ], E1_s[TJ], E2_s[TJ];
    __shared__ float rden[TI];

    const int t    = threadIdx.x;
    const int ib   = blockIdx.x;    // 0..15
    const int head = blockIdx.y;    // 0..3
    const int b    = blockIdx.z;    // 0..3

    const int i_g  = ib * TI + t;
    const int nh_i = (b * N_ + i_g) * H_ + head;
    const float s_i = g_s[nh_i];
    const float A1  = g_A1[nh_i];
    const float A2  = g_A2[nh_i];
    float denom = 0.f;

    // Phase-C mapping
    const int g = t >> 3;     // i-group 0..15
    const int c = t & 7;      // f-chunk 0..7

    unsigned long long acc[8][4];
#pragma unroll
    for (int i = 0; i < 8; i++)
#pragma unroll
        for (int fp = 0; fp < 4; fp++) acc[i][fp] = 0ull;

    const float* adjbase = adj + (size_t)i_g * N_;

    // h-tile load mapping: row jr (0..31), 16 floats at col 'part'
    const int jr   = t >> 2;
    const int part = (t & 3) * 16;

    // prologue: prefetch tile 0 into registers
    float4 hreg[4];
    float nd = 0.f, ne1 = 0.f, ne2 = 0.f;
    {
        const float* hrow = g_h + ((size_t)((b * N_ + jr) * H_ + head)) * FO_ + part;
#pragma unroll
        for (int q = 0; q < 4; q++) hreg[q] = *(const float4*)(hrow + 4 * q);
        if (t < TJ) {
            const int nh_j = (b * N_ + t) * H_ + head;
            nd = g_dv[nh_j]; ne1 = g_E1[nh_j]; ne2 = g_E2[nh_j];
        }
    }

    for (int jt = 0; jt < N_ / TJ; jt++) {
        // issue adj loads for this tile early (independent of smem)
        float4 av[8];
        const float* arow = adjbase + jt * TJ;
#pragma unroll
        for (int q = 0; q < 8; q++) av[q] = *(const float4*)(arow + 4 * q);

        __syncthreads();   // previous FMA phase done reading smem
#pragma unroll
        for (int q = 0; q < 4; q++) *(float4*)&h_s[jr][part + 4 * q] = hreg[q];
        if (t < TJ) { d_s[t] = nd; E1_s[t] = ne1; E2_s[t] = ne2; }
        __syncthreads();

        // prefetch next tile (hidden under phase B + C)
        if (jt + 1 < N_ / TJ) {
            const int j0 = (jt + 1) * TJ;
            const float* hrow = g_h + ((size_t)((b * N_ + j0 + jr) * H_ + head)) * FO_ + part;
#pragma unroll
            for (int q = 0; q < 4; q++) hreg[q] = *(const float4*)(hrow + 4 * q);
            if (t < TJ) {
                const int nh_j = (b * N_ + j0 + t) * H_ + head;
                nd = g_dv[nh_j]; ne1 = g_E1[nh_j]; ne2 = g_E2[nh_j];
            }
        }

        // ---- Phase B: factored softmax weights (no exp!) ----
        const float* afl = (const float*)av;
#pragma unroll
        for (int jj = 0; jj < TJ; jj++) {
            const float a  = afl[jj];
            const float t0 = s_i + d_s[jj];
            float w = (t0 > 0.f) ? (A1 * E1_s[jj]) : (A2 * E2_s[jj]);
            w = (a != 0.f) ? w : 0.f;
            denom += w;
            w_s[jj][t] = w;
        }
        __syncthreads();

        // ---- Phase C: out_tile += w * h, packed f32x2 ----
#pragma unroll 4
        for (int jj = 0; jj < TJ; jj++) {
            const float4 w0 = *(const float4*)&w_s[jj][g * 8];
            const float4 w1 = *(const float4*)&w_s[jj][g * 8 + 4];
            const unsigned long long* hq =
                (const unsigned long long*)&h_s[jj][c * 8];
            unsigned long long hp[4];
            hp[0] = hq[0]; hp[1] = hq[1]; hp[2] = hq[2]; hp[3] = hq[3];

            unsigned long long wd[8];
            wd[0] = dup2(w0.x); wd[1] = dup2(w0.y);
            wd[2] = dup2(w0.z); wd[3] = dup2(w0.w);
            wd[4] = dup2(w1.x); wd[5] = dup2(w1.y);
            wd[6] = dup2(w1.z); wd[7] = dup2(w1.w);
#pragma unroll
            for (int i = 0; i < 8; i++)
#pragma unroll
                for (int fp = 0; fp < 4; fp++) fma2(acc[i][fp], wd[i], hp[fp]);
        }
    }

    rden[t] = 1.0f / denom;
    __syncthreads();

    // store (f-contiguous float4 pairs per i-row)
#pragma unroll
    for (int i = 0; i < 8; i++) {
        const float r  = rden[g * 8 + i];
        const int row  = b * N_ + ib * TI + g * 8 + i;
        float* orow    = out + (size_t)row * HF + head * FO_ + c * 8;
        const float2 p0 = unp2(acc[i][0]);
        const float2 p1 = unp2(acc[i][1]);
        const float2 p2 = unp2(acc[i][2]);
        const float2 p3 = unp2(acc[i][3]);
        *(float4*)(orow)     = make_float4(p0.x * r, p0.y * r, p1.x * r, p1.y * r);
        *(float4*)(orow + 4) = make_float4(p2.x * r, p2.y * r, p3.x * r, p3.y * r);
    }
}

// ---------------- launch ----------------
extern "C" void kernel_launch(void* const* d_in, const int* in_sizes, int n_in,
                              void* d_out, int out_size) {
    (void)in_sizes; (void)n_in; (void)out_size;
    const float* x     = (const float*)d_in[0];
    const float* adj   = (const float*)d_in[1];
    const float* W     = (const float*)d_in[2];
    const float* a_src = (const float*)d_in[3];
    const float* a_dst = (const float*)d_in[4];
    float* out = (float*)d_out;

    gemm_kernel<<<dim3(M_ / 128, HF / 64), 128>>>(x, W);
    attn_coef_kernel<<<(NH * 32) / 256, 256>>>(a_src, a_dst);
    gat_attn_kernel<<<dim3(N_ / TI, H_, B_), 128>>>(adj, out);
}

// round 6
// speedup vs baseline: 1.0031x; 1.0031x over previous
#include <cuda_runtime.h>

// Problem constants
#define B_   4
#define N_   2048
#define FIN  256
#define H_   4
#define FO_  64
#define HF   256               // H_*FO_
#define M_   (B_*N_)           // 8192 rows of h
#define NH   (M_*H_)           // 32768 (node, head) pairs

// Scratch (device globals — no allocation allowed)
__device__ float g_h[M_ * HF];                      // h = x@W, 8 MB
__device__ float g_s[NH], g_dv[NH];
__device__ float g_A1[NH], g_A2[NH], g_E1[NH], g_E2[NH];

// ---------------- packed f32x2 helpers (Blackwell FFMA2) ----------------
__device__ __forceinline__ unsigned long long dup2(float x) {
    unsigned long long d;
    unsigned int u = __float_as_uint(x);
    asm("mov.b64 %0, {%1, %1};" : "=l"(d) : "r"(u));
    return d;
}
__device__ __forceinline__ void fma2(unsigned long long& acc,
                                     unsigned long long a, unsigned long long b) {
    asm("fma.rn.f32x2 %0, %1, %2, %0;" : "+l"(acc) : "l"(a), "l"(b));
}
__device__ __forceinline__ float2 unp2(unsigned long long v) {
    float2 r;
    asm("mov.b64 {%0, %1}, %2;" : "=f"(r.x), "=f"(r.y) : "l"(v));
    return r;
}

// ---------------- Kernel 1: h = x @ W  (8192x256 @ 256x256) ----------------
// 128x64 block tile, 128 threads, 8x8 microtile, BK=16.
__global__ __launch_bounds__(128) void gemm_kernel(const float* __restrict__ x,
                                                   const float* __restrict__ W) {
    __shared__ float As[16][132];   // As[k][m], padded
    __shared__ float Bs[16][68];    // Bs[k][n], padded

    const int t  = threadIdx.x;
    const int m0 = blockIdx.x * 128;
    const int n0 = blockIdx.y * 64;
    const int gm = t >> 3;          // 0..15 -> rows gm*8..+7
    const int gn = t & 7;           // 0..7  -> cols gn*8..+7

    float acc[8][8];
#pragma unroll
    for (int i = 0; i < 8; i++)
#pragma unroll
        for (int j = 0; j < 8; j++) acc[i][j] = 0.f;

    for (int k0 = 0; k0 < FIN; k0 += 16) {
        // stage loads into registers
        float4 xv[4];
        const float* xrow = x + (size_t)(m0 + t) * FIN + k0;
#pragma unroll
        for (int q = 0; q < 4; q++) xv[q] = *(const float4*)(xrow + 4 * q);

        float4 wv0, wv1;
        {
            const int kr = t >> 3;            // 0..15
            const int cp = (t & 7) * 8;       // 0..56
            const float* wrow = W + (size_t)(k0 + kr) * HF + n0 + cp;
            wv0 = *(const float4*)(wrow);
            wv1 = *(const float4*)(wrow + 4);
        }

        __syncthreads();   // previous compute finished reading smem
#pragma unroll
        for (int q = 0; q < 4; q++) {
            As[4 * q + 0][t] = xv[q].x;
            As[4 * q + 1][t] = xv[q].y;
            As[4 * q + 2][t] = xv[q].z;
            As[4 * q + 3][t] = xv[q].w;
        }
        {
            const int kr = t >> 3;
            const int cp = (t & 7) * 8;
            *(float4*)&Bs[kr][cp]     = wv0;
            *(float4*)&Bs[kr][cp + 4] = wv1;
        }
        __syncthreads();

#pragma unroll
        for (int kk = 0; kk < 16; kk++) {
            float a[8], b[8];
            *(float4*)(a)     = *(const float4*)&As[kk][gm * 8];
            *(float4*)(a + 4) = *(const float4*)&As[kk][gm * 8 + 4];
            *(float4*)(b)     = *(const float4*)&Bs[kk][gn * 8];
            *(float4*)(b + 4) = *(const float4*)&Bs[kk][gn * 8 + 4];
#pragma unroll
            for (int i = 0; i < 8; i++)
#pragma unroll
                for (int j = 0; j < 8; j++) acc[i][j] += a[i] * b[j];
        }
    }

#pragma unroll
    for (int i = 0; i < 8; i++) {
        float* orow = g_h + (size_t)(m0 + gm * 8 + i) * HF + n0 + gn * 8;
        *(float4*)(orow)     = make_float4(acc[i][0], acc[i][1], acc[i][2], acc[i][3]);
        *(float4*)(orow + 4) = make_float4(acc[i][4], acc[i][5], acc[i][6], acc[i][7]);
    }
}

// ---------------- Kernel 2: attention coefficients + exp factors ----------------
// warp per (node, head): s = h . a_src, d = h . a_dst, then exp factors.
__global__ __launch_bounds__(256) void attn_coef_kernel(const float* __restrict__ a_src,
                                                        const float* __restrict__ a_dst) {
    const int nh   = (blockIdx.x * blockDim.x + threadIdx.x) >> 5;   // (b*N+n)*H + head
    const int lane = threadIdx.x & 31;
    if (nh >= NH) return;
    const int head = nh & (H_ - 1);

    const float* hrow = g_h + (size_t)nh * FO_;
    const float v0 = hrow[lane];
    const float v1 = hrow[lane + 32];
    const float* as = a_src + head * FO_;
    const float* ad = a_dst + head * FO_;
    float ps = v0 * as[lane] + v1 * as[lane + 32];
    float pd = v0 * ad[lane] + v1 * ad[lane + 32];
#pragma unroll
    for (int o = 16; o > 0; o >>= 1) {
        ps += __shfl_xor_sync(0xffffffffu, ps, o);
        pd += __shfl_xor_sync(0xffffffffu, pd, o);
    }
    if (lane == 0) {
        g_s[nh]  = ps;
        g_A1[nh] = expf(ps);
        g_A2[nh] = expf(0.2f * ps);
        g_dv[nh] = pd;
        g_E1[nh] = expf(pd);
        g_E2[nh] = expf(0.2f * pd);
    }
}

// ---------------- Kernel 3: masked-softmax attention + P@V ----------------
// Block = (b, head, i-block of 128). 128 threads.
// Phase B: thread t owns row i=t -> weights + private denominator (no atomics).
// Phase C: thread -> 8i x 8f microtile, packed f32x2 FMAs.
#define TI 128
#define TJ 32

__global__ __launch_bounds__(128, 2) void gat_attn_kernel(const float* __restrict__ adj,
                                                          float* __restrict__ out) {
    __shared__ __align__(16) float h_s[TJ][68];     // 64 used + pad
    __shared__ __align__(16) float w_s[TJ][TI];
    __shared__ float d_s[TJ], E1_s[TJ], E2_s[TJ];
    __shared__ float rden[TI];

    const int t    = threadIdx.x;
    const int ib   = blockIdx.x;    // 0..15
    const int head = blockIdx.y;    // 0..3
    const int b    = blockIdx.z;    // 0..3

    const int i_g  = ib * TI + t;
    const int nh_i = (b * N_ + i_g) * H_ + head;
    const float s_i = g_s[nh_i];
    const float A1  = g_A1[nh_i];
    const float A2  = g_A2[nh_i];
    float denom = 0.f;

    // Phase-C mapping
    const int g = t >> 3;     // i-group 0..15
    const int c = t & 7;      // f-chunk 0..7

    unsigned long long acc[8][4];
#pragma unroll
    for (int i = 0; i < 8; i++)
#pragma unroll
        for (int fp = 0; fp < 4; fp++) acc[i][fp] = 0ull;

    const float* adjbase = adj + (size_t)i_g * N_;

    // h-tile load mapping: row jr (0..31), 16 floats at col 'part'
    const int jr   = t >> 2;
    const int part = (t & 3) * 16;

    // prologue: prefetch tile 0 into registers
    float4 hreg[4];
    float nd = 0.f, ne1 = 0.f, ne2 = 0.f;
    {
        const float* hrow = g_h + ((size_t)((b * N_ + jr) * H_ + head)) * FO_ + part;
#pragma unroll
        for (int q = 0; q < 4; q++) hreg[q] = *(const float4*)(hrow + 4 * q);
        if (t < TJ) {
            const int nh_j = (b * N_ + t) * H_ + head;
            nd = g_dv[nh_j]; ne1 = g_E1[nh_j]; ne2 = g_E2[nh_j];
        }
    }

    for (int jt = 0; jt < N_ / TJ; jt++) {
        // issue adj loads for this tile early (independent of smem)
        float4 av[8];
        const float* arow = adjbase + jt * TJ;
#pragma unroll
        for (int q = 0; q < 8; q++) av[q] = *(const float4*)(arow + 4 * q);

        __syncthreads();   // previous FMA phase done reading smem
#pragma unroll
        for (int q = 0; q < 4; q++) *(float4*)&h_s[jr][part + 4 * q] = hreg[q];
        if (t < TJ) { d_s[t] = nd; E1_s[t] = ne1; E2_s[t] = ne2; }
        __syncthreads();

        // prefetch next tile (hidden under phase B + C)
        if (jt + 1 < N_ / TJ) {
            const int j0 = (jt + 1) * TJ;
            const float* hrow = g_h + ((size_t)((b * N_ + j0 + jr) * H_ + head)) * FO_ + part;
#pragma unroll
            for (int q = 0; q < 4; q++) hreg[q] = *(const float4*)(hrow + 4 * q);
            if (t < TJ) {
                const int nh_j = (b * N_ + j0 + t) * H_ + head;
                nd = g_dv[nh_j]; ne1 = g_E1[nh_j]; ne2 = g_E2[nh_j];
            }
        }

        // ---- Phase B: factored softmax weights (no exp!) ----
        const float* afl = (const float*)av;
#pragma unroll
        for (int jj = 0; jj < TJ; jj++) {
            const float a  = afl[jj];
            const float t0 = s_i + d_s[jj];
            float w = (t0 > 0.f) ? (A1 * E1_s[jj]) : (A2 * E2_s[jj]);
            w = (a != 0.f) ? w : 0.f;
            denom += w;
            w_s[jj][t] = w;
        }
        __syncthreads();

        // ---- Phase C: out_tile += w * h, packed f32x2 ----
#pragma unroll 4
        for (int jj = 0; jj < TJ; jj++) {
            const float4 w0 = *(const float4*)&w_s[jj][g * 8];
            const float4 w1 = *(const float4*)&w_s[jj][g * 8 + 4];
            const unsigned long long* hq =
                (const unsigned long long*)&h_s[jj][c * 8];
            unsigned long long hp[4];
            hp[0] = hq[0]; hp[1] = hq[1]; hp[2] = hq[2]; hp[3] = hq[3];

            unsigned long long wd[8];
            wd[0] = dup2(w0.x); wd[1] = dup2(w0.y);
            wd[2] = dup2(w0.z); wd[3] = dup2(w0.w);
            wd[4] = dup2(w1.x); wd[5] = dup2(w1.y);
            wd[6] = dup2(w1.z); wd[7] = dup2(w1.w);
#pragma unroll
            for (int i = 0; i < 8; i++)
#pragma unroll
                for (int fp = 0; fp < 4; fp++) fma2(acc[i][fp], wd[i], hp[fp]);
        }
    }

    rden[t] = 1.0f / denom;
    __syncthreads();

    // store (f-contiguous float4 pairs per i-row)
#pragma unroll
    for (int i = 0; i < 8; i++) {
        const float r  = rden[g * 8 + i];
        const int row  = b * N_ + ib * TI + g * 8 + i;
        float* orow    = out + (size_t)row * HF + head * FO_ + c * 8;
        const float2 p0 = unp2(acc[i][0]);
        const float2 p1 = unp2(acc[i][1]);
        const float2 p2 = unp2(acc[i][2]);
        const float2 p3 = unp2(acc[i][3]);
        *(float4*)(orow)     = make_float4(p0.x * r, p0.y * r, p1.x * r, p1.y * r);
        *(float4*)(orow + 4) = make_float4(p2.x * r, p2.y * r, p3.x * r, p3.y * r);
    }
}

// ---------------- launch ----------------
extern "C" void kernel_launch(void* const* d_in, const int* in_sizes, int n_in,
                              void* d_out, int out_size) {
    (void)in_sizes; (void)n_in; (void)out_size;
    const float* x     = (const float*)d_in[0];
    const float* adj   = (const float*)d_in[1];
    const float* W     = (const float*)d_in[2];
    const float* a_src = (const float*)d_in[3];
    const float* a_dst = (const float*)d_in[4];
    float* out = (float*)d_out;

    gemm_kernel<<<dim3(M_ / 128, HF / 64), 128>>>(x, W);
    attn_coef_kernel<<<(NH * 32) / 256, 256>>>(a_src, a_dst);
    gat_attn_kernel<<<dim3(N_ / TI, H_, B_), 128>>>(adj, out);
}